// round 11
// baseline (speedup 1.0000x reference)
#include <cuda_runtime.h>
#include <cuda_bf16.h>
#include <cstdint>

// Problem constants
#define BT    65536   // B*T
#define CDIM  128
#define HDIM  64
#define TSEQ  512
#define SCALE 0.088388347648318447f   // 1/sqrt(128)

// q/k scratch bf16 hi/lo in [B][T][H]; v scratch bf16 hi/lo in [B][H][T]
__device__ __nv_bfloat16 g_qhi[BT * HDIM];
__device__ __nv_bfloat16 g_qlo[BT * HDIM];
__device__ __nv_bfloat16 g_khi[BT * HDIM];
__device__ __nv_bfloat16 g_klo[BT * HDIM];
__device__ __nv_bfloat16 g_vhi[BT * HDIM];
__device__ __nv_bfloat16 g_vlo[BT * HDIM];

// pre-split weight images (k0 output), row-major [n][k], k stride 128 bf16
__device__ __nv_bfloat16 g_wgh[128 * 128];
__device__ __nv_bfloat16 g_wgl[128 * 128];
__device__ __nv_bfloat16 g_wqkvh[192 * 128];
__device__ __nv_bfloat16 g_wqkvl[192 * 128];

// split-K attention partials: 2560 parts x 128 rows
__device__ float g_po[2560 * 128 * 64];   // unnormalized partial O
__device__ float g_pm[2560 * 128];        // per-row max
__device__ float g_pl[2560 * 128];        // per-row sum

// ---------------------------------------------------------------------------
// helpers
// ---------------------------------------------------------------------------
__device__ __forceinline__ uint32_t smem_u32(const void* p) {
    uint32_t a;
    asm("{ .reg .u64 t; cvta.to.shared.u64 t, %1; cvt.u32.u64 %0, t; }"
        : "=r"(a) : "l"(p));
    return a;
}
__device__ __forceinline__ uint32_t pack_bf16(float lo, float hi) {
    uint32_t r;
    asm("cvt.rn.bf16x2.f32 %0, %1, %2;" : "=r"(r) : "f"(hi), "f"(lo));
    return r;
}
__device__ __forceinline__ float bf16_residual(float v) {
    return v - __bfloat162float(__float2bfloat16(v));
}
__device__ __forceinline__ void split_pack(float v0, float v1,
                                           uint32_t& hi, uint32_t& lo) {
    __nv_bfloat16 h0 = __float2bfloat16(v0);
    __nv_bfloat16 h1 = __float2bfloat16(v1);
    __nv_bfloat162 hh; hh.x = h0; hh.y = h1;
    hi = *reinterpret_cast<uint32_t*>(&hh);
    lo = pack_bf16(v0 - __bfloat162float(h0), v1 - __bfloat162float(h1));
}
__device__ __forceinline__ void mma_bf16(float* d, const uint32_t* a,
                                         const uint32_t* b) {
    asm volatile(
        "mma.sync.aligned.m16n8k16.row.col.f32.bf16.bf16.f32 "
        "{%0,%1,%2,%3}, {%4,%5,%6,%7}, {%8,%9}, {%0,%1,%2,%3};"
        : "+f"(d[0]), "+f"(d[1]), "+f"(d[2]), "+f"(d[3])
        : "r"(a[0]), "r"(a[1]), "r"(a[2]), "r"(a[3]), "r"(b[0]), "r"(b[1]));
}
__device__ __forceinline__ void cp_async16(uint32_t smem_dst, const void* gsrc) {
    asm volatile("cp.async.cg.shared.global [%0], [%1], 16;"
                 :: "r"(smem_dst), "l"(gsrc) : "memory");
}
#define CP_COMMIT() asm volatile("cp.async.commit_group;" ::: "memory")
#define CP_WAIT0()  asm volatile("cp.async.wait_group 0;" ::: "memory")

// ---------------------------------------------------------------------------
// Kernel 0: one-time weight split into bf16 hi/lo global images.
// ---------------------------------------------------------------------------
__global__ __launch_bounds__(256, 4)
void head_k0_split(const float* __restrict__ Wg,
                   const float* __restrict__ Wk,
                   const float* __restrict__ Wq,
                   const float* __restrict__ Wv)
{
    int i = blockIdx.x * 256 + threadIdx.x;
    if (i < 128 * 128) {
        int d = i >> 7, c = i & 127;
        float v = Wg[c * 128 + d];
        __nv_bfloat16 h = __float2bfloat16(v);
        g_wgh[i] = h;
        g_wgl[i] = __float2bfloat16(v - __bfloat162float(h));
    } else if (i < 128 * 128 + 192 * 128) {
        int j = i - 128 * 128;
        int e = j >> 7, c = j & 127;
        float v;
        if (e < 64)       v = Wq[c * 64 + e];
        else if (e < 128) v = Wk[c * 64 + (e - 64)];
        else              v = Wv[c * 64 + (e - 128)];
        __nv_bfloat16 h = __float2bfloat16(v);
        g_wqkvh[j] = h;
        g_wqkvl[j] = __float2bfloat16(v - __bfloat162float(h));
    }
}

// ---------------------------------------------------------------------------
// Kernel 1: gate GEMM + sigmoid-gate + QKV GEMM (bf16x3 HMMA).
// 512 threads = 16 warps = 8 row-groups x 2 N-halves; cp.async smem weights.
// (unchanged from the 158us-passing version)
// ---------------------------------------------------------------------------
#define K1_SMEM 174592

__global__ __launch_bounds__(512, 1)
void head_k1_gate_qkv(const float* __restrict__ x,
                      const float* __restrict__ bg)
{
    extern __shared__ char smc[];
    const uint32_t sbase = smem_u32(smc);
    __nv_bfloat16* AH = reinterpret_cast<__nv_bfloat16*>(smc);
    __nv_bfloat16* AL = reinterpret_cast<__nv_bfloat16*>(smc + 34816);
    float*         bgs = reinterpret_cast<float*>(smc + 174080);
    float*         vT  = reinterpret_cast<float*>(smc);          // overlay

    uint32_t* AHw = reinterpret_cast<uint32_t*>(AH);
    uint32_t* ALw = reinterpret_cast<uint32_t*>(AL);
    const uint32_t* BHw = reinterpret_cast<const uint32_t*>(smc + 69632);
    const uint32_t* BLw = reinterpret_cast<const uint32_t*>(smc + 121856);

    const int tid   = threadIdx.x;
    const int wid   = tid >> 5;
    const int lane  = tid & 31;
    const int g     = lane >> 2;
    const int qq    = lane & 3;
    const int q2    = qq * 2;
    const int rg    = wid >> 1;         // row group 0..7
    const int nh    = wid & 1;          // N half
    const int wbase = rg * 16;
    const int tok0  = blockIdx.x * 128;
    const int bb    = tok0 >> 9;
    const int t0    = tok0 & 511;

    // ---- issue Wg hi/lo -> B via cp.async ----
    {
        const char* wh = reinterpret_cast<const char*>(g_wgh);
        const char* wl = reinterpret_cast<const char*>(g_wgl);
        for (int i = tid; i < 2048; i += 512) {
            int row = i >> 4, ch = i & 15;
            uint32_t dof = (uint32_t)(row * 272 + ch * 16);
            cp_async16(sbase + 69632 + dof,  wh + row * 256 + ch * 16);
            cp_async16(sbase + 121856 + dof, wl + row * 256 + ch * 16);
        }
        CP_COMMIT();
    }

    // ---- load + split x -> A hi/lo (float4 vectorized) ----
    for (int i = tid; i < 4096; i += 512) {
        int t = i >> 5, c4 = (i & 31) * 4;
        float4 xv = *reinterpret_cast<const float4*>(
                        x + (size_t)(tok0 + t) * CDIM + c4);
        uint32_t h0, l0w, h1, l1w;
        split_pack(xv.x, xv.y, h0, l0w);
        split_pack(xv.z, xv.w, h1, l1w);
        int widx = t * 68 + (c4 >> 1);
        AHw[widx] = h0; AHw[widx + 1] = h1;
        ALw[widx] = l0w; ALw[widx + 1] = l1w;
    }
    if (tid < 128) bgs[tid] = bg[tid];
    CP_WAIT0();
    __syncthreads();

    // ---- phase 1: gate = x @ Wg (16 rows x 64 cols per warp) ----
    float acc[8][4];
    #pragma unroll
    for (int j = 0; j < 8; j++)
        #pragma unroll
        for (int t = 0; t < 4; t++) acc[j][t] = 0.f;

    #pragma unroll
    for (int kk = 0; kk < 8; ++kk) {
        const int kw = kk * 8 + qq;
        const int r0 = wbase + g;
        uint32_t ah[4], al[4];
        ah[0] = AHw[r0 * 68 + kw];       ah[1] = AHw[(r0 + 8) * 68 + kw];
        ah[2] = AHw[r0 * 68 + kw + 4];   ah[3] = AHw[(r0 + 8) * 68 + kw + 4];
        al[0] = ALw[r0 * 68 + kw];       al[1] = ALw[(r0 + 8) * 68 + kw];
        al[2] = ALw[r0 * 68 + kw + 4];   al[3] = ALw[(r0 + 8) * 68 + kw + 4];
        #pragma unroll
        for (int j = 0; j < 8; ++j) {
            const int n = nh * 64 + j * 8 + g;
            uint32_t bh[2] = { BHw[n * 68 + kw], BHw[n * 68 + kw + 4] };
            uint32_t bl[2] = { BLw[n * 68 + kw], BLw[n * 68 + kw + 4] };
            mma_bf16(acc[j], ah, bh);
            mma_bf16(acc[j], ah, bl);
            mma_bf16(acc[j], al, bh);
        }
    }
    __syncthreads();   // all warps done reading B (Wg)

    // ---- issue W[q|k|v] hi/lo -> B, overlapped with gate epilogue ----
    {
        const char* wh = reinterpret_cast<const char*>(g_wqkvh);
        const char* wl = reinterpret_cast<const char*>(g_wqkvl);
        for (int i = tid; i < 3072; i += 512) {
            int row = i >> 4, ch = i & 15;
            uint32_t dof = (uint32_t)(row * 272 + ch * 16);
            cp_async16(sbase + 69632 + dof,  wh + row * 256 + ch * 16);
            cp_async16(sbase + 121856 + dof, wl + row * 256 + ch * 16);
        }
        CP_COMMIT();
    }

    // ---- gate epilogue: xg = x * sigmoid(gate + bg), rewrite A (own cells) ----
    #pragma unroll
    for (int j = 0; j < 8; ++j) {
        const int col = nh * 64 + j * 8 + q2;
        #pragma unroll
        for (int hf = 0; hf < 2; ++hf) {
            const int r = wbase + g + hf * 8;
            __nv_bfloat162 hw = *reinterpret_cast<__nv_bfloat162*>(&AH[r * 136 + col]);
            __nv_bfloat162 lw = *reinterpret_cast<__nv_bfloat162*>(&AL[r * 136 + col]);
            float x0 = __bfloat162float(hw.x) + __bfloat162float(lw.x);
            float x1 = __bfloat162float(hw.y) + __bfloat162float(lw.y);
            float c0 = acc[j][hf * 2 + 0], c1 = acc[j][hf * 2 + 1];
            float g0 = 1.f / (1.f + __expf(-(c0 + bgs[col])));
            float g1 = 1.f / (1.f + __expf(-(c1 + bgs[col + 1])));
            uint32_t hiw, low;
            split_pack(x0 * g0, x1 * g1, hiw, low);
            *reinterpret_cast<uint32_t*>(&AH[r * 136 + col]) = hiw;
            *reinterpret_cast<uint32_t*>(&AL[r * 136 + col]) = low;
        }
    }
    CP_WAIT0();
    __syncthreads();

    // ---- phase 2: [q|k|v] = xg @ W (16 rows x 96 cols per warp) ----
    float acc2[12][4];
    #pragma unroll
    for (int j = 0; j < 12; j++)
        #pragma unroll
        for (int t = 0; t < 4; t++) acc2[j][t] = 0.f;

    #pragma unroll
    for (int kk = 0; kk < 8; ++kk) {
        const int kw = kk * 8 + qq;
        const int r0 = wbase + g;
        uint32_t ah[4], al[4];
        ah[0] = AHw[r0 * 68 + kw];       ah[1] = AHw[(r0 + 8) * 68 + kw];
        ah[2] = AHw[r0 * 68 + kw + 4];   ah[3] = AHw[(r0 + 8) * 68 + kw + 4];
        al[0] = ALw[r0 * 68 + kw];       al[1] = ALw[(r0 + 8) * 68 + kw];
        al[2] = ALw[r0 * 68 + kw + 4];   al[3] = ALw[(r0 + 8) * 68 + kw + 4];
        #pragma unroll
        for (int j = 0; j < 12; ++j) {
            const int n = nh * 96 + j * 8 + g;
            uint32_t bh[2] = { BHw[n * 68 + kw], BHw[n * 68 + kw + 4] };
            uint32_t bl[2] = { BLw[n * 68 + kw], BLw[n * 68 + kw + 4] };
            mma_bf16(acc2[j], ah, bh);
            mma_bf16(acc2[j], ah, bl);
            mma_bf16(acc2[j], al, bh);
        }
    }
    __syncthreads();   // all A reads done before vT overlay writes

    // ---- epilogue: route by e = nh*96 + j*8 + q2 ----
    uint32_t* gqh = reinterpret_cast<uint32_t*>(g_qhi);
    uint32_t* gql = reinterpret_cast<uint32_t*>(g_qlo);
    uint32_t* gkh = reinterpret_cast<uint32_t*>(g_khi);
    uint32_t* gkl = reinterpret_cast<uint32_t*>(g_klo);
    #pragma unroll
    for (int j = 0; j < 12; ++j) {
        const int e = nh * 96 + j * 8 + q2;
        if (e < 64) {            // q (pre-scaled)
            #pragma unroll
            for (int hf = 0; hf < 2; ++hf) {
                const int r = wbase + g + hf * 8;
                uint32_t hiw, low;
                split_pack(acc2[j][hf * 2] * SCALE, acc2[j][hf * 2 + 1] * SCALE,
                           hiw, low);
                size_t widx = (size_t)(tok0 + r) * 32 + (e >> 1);
                gqh[widx] = hiw; gql[widx] = low;
            }
        } else if (e < 128) {    // k
            const int h = e - 64;
            #pragma unroll
            for (int hf = 0; hf < 2; ++hf) {
                const int r = wbase + g + hf * 8;
                uint32_t hiw, low;
                split_pack(acc2[j][hf * 2], acc2[j][hf * 2 + 1], hiw, low);
                size_t widx = (size_t)(tok0 + r) * 32 + (h >> 1);
                gkh[widx] = hiw; gkl[widx] = low;
            }
        } else {                 // v -> vT smem (transpose)
            const int h = e - 128;
            const int r = wbase + g;
            vT[h * 132 + r]           = acc2[j][0];
            vT[(h + 1) * 132 + r]     = acc2[j][1];
            vT[h * 132 + r + 8]       = acc2[j][2];
            vT[(h + 1) * 132 + r + 8] = acc2[j][3];
        }
    }
    __syncthreads();

    // ---- v: coalesced bf16 hi/lo stores to [B][H][T] ----
    uint32_t* gvh = reinterpret_cast<uint32_t*>(g_vhi);
    uint32_t* gvl = reinterpret_cast<uint32_t*>(g_vlo);
    for (int i = tid; i < 64 * 64; i += 512) {
        int h = i >> 6, tw = i & 63;
        int t = tw * 2;
        uint32_t hiw, low;
        split_pack(vT[h * 132 + t], vT[h * 132 + t + 1], hiw, low);
        size_t widx = ((size_t)bb * 64 + h) * 256 + ((t0 + t) >> 1);
        gvh[widx] = hiw; gvl[widx] = low;
    }
}

// ---------------------------------------------------------------------------
// Kernel 2: split-K flash attention PARTIAL. One CTA per (b, qtile, ktile,
// key-half): grid 2560 x 256 threads = 8 warps x 16 q-rows, 64 keys each.
// Writes unnormalized (o, m, l) partials to global scratch.
// smem words: QH 4608 @0, QL @4608, KH 2304 @9216, KL @11520,
//             VH 2304 @13824, VL @16128. total 18432 words = 73728 B.
// ---------------------------------------------------------------------------
#define K2_SMEM 73728

__global__ __launch_bounds__(256, 2)
void head_k2_part()
{
    extern __shared__ char smc[];
    const uint32_t sbase = smem_u32(smc);
    uint32_t* S = reinterpret_cast<uint32_t*>(smc);
    const uint32_t* QHw = S;
    const uint32_t* QLw = S + 4608;
    const uint32_t* KHw = S + 9216;
    const uint32_t* KLw = S + 11520;
    const uint32_t* VHw = S + 13824;
    const uint32_t* VLw = S + 16128;

    const int tid  = threadIdx.x;
    const int wid  = tid >> 5;          // 0..7 = q group
    const int lane = tid & 31;
    const int g    = lane >> 2;
    const int qq   = lane & 3;
    const int q2   = qq * 2;
    const int qg   = wid;
    const int wbase = qg * 16;

    const int pid = blockIdx.x;         // 0..2559
    const int b   = pid / 20;
    const int u20 = pid % 20;
    const int u   = u20 >> 1;
    const int kh  = u20 & 1;
    int qt, jt;
    if (u < 1)      { qt = 0; jt = 0; }
    else if (u < 3) { qt = 1; jt = u - 1; }
    else if (u < 6) { qt = 2; jt = u - 3; }
    else            { qt = 3; jt = u - 6; }
    const int q0 = qt * 128;
    const int k0 = jt * 128;

    const uint32_t* gqh = reinterpret_cast<const uint32_t*>(g_qhi);
    const uint32_t* gql = reinterpret_cast<const uint32_t*>(g_qlo);
    const uint32_t* gkh = reinterpret_cast<const uint32_t*>(g_khi);
    const uint32_t* gkl = reinterpret_cast<const uint32_t*>(g_klo);
    const uint32_t* gvh = reinterpret_cast<const uint32_t*>(g_vhi);
    const uint32_t* gvl = reinterpret_cast<const uint32_t*>(g_vlo);

    // ---- cp.async loads: Q (128x32w), K half (64x32w), V half (64x32w) ----
    {
        size_t qbase = ((size_t)b * 512 + q0) * 32;
        for (int i = tid; i < 1024; i += 256) {
            int row = i >> 3, cw = (i & 7) * 4;
            uint32_t dof = (uint32_t)(row * 36 + cw) * 4;
            cp_async16(sbase + dof,            gqh + qbase + row * 32 + cw);
            cp_async16(sbase + 4608 * 4 + dof, gql + qbase + row * 32 + cw);
        }
        size_t kbase = ((size_t)b * 512 + k0 + kh * 64) * 32;
        for (int i = tid; i < 512; i += 256) {
            int row = i >> 3, cw = (i & 7) * 4;
            uint32_t dof = (uint32_t)(9216 + row * 36 + cw) * 4;
            cp_async16(sbase + dof,            gkh + kbase + row * 32 + cw);
            cp_async16(sbase + dof + 2304 * 4, gkl + kbase + row * 32 + cw);
        }
        size_t vbase = (size_t)b * 64 * 256 + (k0 >> 1) + kh * 32;
        for (int i = tid; i < 512; i += 256) {
            int h = i >> 3, cw = (i & 7) * 4;
            uint32_t dof = (uint32_t)(13824 + h * 36 + cw) * 4;
            cp_async16(sbase + dof,            gvh + vbase + h * 256 + cw);
            cp_async16(sbase + dof + 2304 * 4, gvl + vbase + h * 256 + cw);
        }
        CP_COMMIT();
    }
    CP_WAIT0();
    __syncthreads();

    const bool diag   = (qt == jt);
    const bool active = !(diag && kh == 1 && qg < 4);

    float o[8][4];
    #pragma unroll
    for (int j = 0; j < 8; j++)
        #pragma unroll
        for (int t = 0; t < 4; t++) o[j][t] = 0.f;
    float m0 = -1e30f, m1 = -1e30f, l0 = 0.f, l1 = 0.f;

    if (active) {
        // ---- S = Q K^T (16 rows x 64 keys) ----
        float s[8][4];
        #pragma unroll
        for (int j = 0; j < 8; j++)
            #pragma unroll
            for (int t = 0; t < 4; t++) s[j][t] = 0.f;

        #pragma unroll
        for (int kk = 0; kk < 4; ++kk) {
            const int kw = kk * 8 + qq;
            const int r0w = wbase + g;
            uint32_t qh[4], ql[4];
            qh[0] = QHw[r0w * 36 + kw];     qh[1] = QHw[(r0w + 8) * 36 + kw];
            qh[2] = QHw[r0w * 36 + kw + 4]; qh[3] = QHw[(r0w + 8) * 36 + kw + 4];
            ql[0] = QLw[r0w * 36 + kw];     ql[1] = QLw[(r0w + 8) * 36 + kw];
            ql[2] = QLw[r0w * 36 + kw + 4]; ql[3] = QLw[(r0w + 8) * 36 + kw + 4];
            #pragma unroll
            for (int j = 0; j < 8; ++j) {
                const int n = j * 8 + g;
                uint32_t bh[2] = { KHw[n * 36 + kw], KHw[n * 36 + kw + 4] };
                uint32_t bl[2] = { KLw[n * 36 + kw], KLw[n * 36 + kw + 4] };
                mma_bf16(s[j], qh, bh);
                mma_bf16(s[j], qh, bl);
                mma_bf16(s[j], ql, bh);
            }
        }

        // ---- causal mask (diagonal tile only) ----
        if (diag) {
            const int r0 = q0 + wbase + g;
            const int cb = k0 + kh * 64;
            #pragma unroll
            for (int j = 0; j < 8; ++j) {
                const int c0 = cb + j * 8 + q2;
                if (c0     > r0)     s[j][0] = -1e30f;
                if (c0 + 1 > r0)     s[j][1] = -1e30f;
                if (c0     > r0 + 8) s[j][2] = -1e30f;
                if (c0 + 1 > r0 + 8) s[j][3] = -1e30f;
            }
        }

        // ---- single-tile softmax (quad shuffles per row) ----
        float mx0 = -1e30f, mx1 = -1e30f;
        #pragma unroll
        for (int j = 0; j < 8; ++j) {
            mx0 = fmaxf(mx0, fmaxf(s[j][0], s[j][1]));
            mx1 = fmaxf(mx1, fmaxf(s[j][2], s[j][3]));
        }
        mx0 = fmaxf(mx0, __shfl_xor_sync(0xffffffffu, mx0, 1));
        mx0 = fmaxf(mx0, __shfl_xor_sync(0xffffffffu, mx0, 2));
        mx1 = fmaxf(mx1, __shfl_xor_sync(0xffffffffu, mx1, 1));
        mx1 = fmaxf(mx1, __shfl_xor_sync(0xffffffffu, mx1, 2));
        m0 = mx0; m1 = mx1;
        float s0 = 0.f, s1 = 0.f;
        #pragma unroll
        for (int j = 0; j < 8; ++j) {
            s[j][0] = __expf(s[j][0] - m0); s0 += s[j][0];
            s[j][1] = __expf(s[j][1] - m0); s0 += s[j][1];
            s[j][2] = __expf(s[j][2] - m1); s1 += s[j][2];
            s[j][3] = __expf(s[j][3] - m1); s1 += s[j][3];
        }
        s0 += __shfl_xor_sync(0xffffffffu, s0, 1);
        s0 += __shfl_xor_sync(0xffffffffu, s0, 2);
        s1 += __shfl_xor_sync(0xffffffffu, s1, 1);
        s1 += __shfl_xor_sync(0xffffffffu, s1, 2);
        l0 = s0; l1 = s1;

        // ---- O = P @ V over 64 keys ----
        #pragma unroll
        for (int kk2 = 0; kk2 < 4; ++kk2) {
            const int j0 = kk2 * 2, j1 = j0 + 1;
            uint32_t ah[4], al[4];
            ah[0] = pack_bf16(s[j0][0], s[j0][1]);
            ah[1] = pack_bf16(s[j0][2], s[j0][3]);
            ah[2] = pack_bf16(s[j1][0], s[j1][1]);
            ah[3] = pack_bf16(s[j1][2], s[j1][3]);
            al[0] = pack_bf16(bf16_residual(s[j0][0]), bf16_residual(s[j0][1]));
            al[1] = pack_bf16(bf16_residual(s[j0][2]), bf16_residual(s[j0][3]));
            al[2] = pack_bf16(bf16_residual(s[j1][0]), bf16_residual(s[j1][1]));
            al[3] = pack_bf16(bf16_residual(s[j1][2]), bf16_residual(s[j1][3]));
            const int kwv = kk2 * 8 + qq;
            #pragma unroll
            for (int jn = 0; jn < 8; ++jn) {
                const int hN = jn * 8 + g;
                uint32_t vh[2] = { VHw[hN * 36 + kwv], VHw[hN * 36 + kwv + 4] };
                uint32_t vl[2] = { VLw[hN * 36 + kwv], VLw[hN * 36 + kwv + 4] };
                mma_bf16(o[jn], ah, vh);
                mma_bf16(o[jn], ah, vl);
                mma_bf16(o[jn], al, vh);
            }
        }
    }

    // ---- write partial (o unnormalized, m, l) ----
    {
        const int r0 = wbase + g, r1 = r0 + 8;
        float* po = g_po + (size_t)pid * (128 * 64);
        #pragma unroll
        for (int jn = 0; jn < 8; ++jn) {
            const int h = jn * 8 + q2;
            *reinterpret_cast<float2*>(po + r0 * 64 + h) =
                make_float2(o[jn][0], o[jn][1]);
            *reinterpret_cast<float2*>(po + r1 * 64 + h) =
                make_float2(o[jn][2], o[jn][3]);
        }
        if (qq == 0) {
            g_pm[pid * 128 + r0] = m0;  g_pl[pid * 128 + r0] = l0;
            g_pm[pid * 128 + r1] = m1;  g_pl[pid * 128 + r1] = l1;
        }
    }
}

// ---------------------------------------------------------------------------
// Kernel 3: merge partials. grid (4 qtiles, 128 batches) x 256 threads.
// Each (b,qt) has np = 2*(qt+1) partials at pids b*20 + (tb[qt]+j)*2 + kh.
// ---------------------------------------------------------------------------
__global__ __launch_bounds__(256, 4)
void head_k3_merge(float* __restrict__ out)
{
    const int qt = blockIdx.x;
    const int b  = blockIdx.y;
    const int tb = (qt == 0) ? 0 : (qt == 1) ? 1 : (qt == 2) ? 3 : 6;
    const int np = (qt + 1) * 2;
    const int pid0 = b * 20 + tb * 2;

    const int t    = threadIdx.x;
    const int row  = t >> 1;
    const int half = (t & 1) * 32;

    float mp[8], ap[8];
    float mstar = -1e30f;
    for (int p = 0; p < np; ++p) {
        mp[p] = g_pm[(pid0 + p) * 128 + row];
        mstar = fmaxf(mstar, mp[p]);
    }
    float l = 0.f;
    for (int p = 0; p < np; ++p) {
        ap[p] = __expf(mp[p] - mstar);
        l += g_pl[(pid0 + p) * 128 + row] * ap[p];
    }
    const float inv = 1.f / l;

    const size_t obase = ((size_t)b * 512 + qt * 128 + row) * 64 + half;
    #pragma unroll
    for (int c = 0; c < 32; c += 4) {
        float4 acc = make_float4(0.f, 0.f, 0.f, 0.f);
        for (int p = 0; p < np; ++p) {
            const float4 v = *reinterpret_cast<const float4*>(
                g_po + ((size_t)(pid0 + p) * 128 + row) * 64 + half + c);
            acc.x += v.x * ap[p]; acc.y += v.y * ap[p];
            acc.z += v.z * ap[p]; acc.w += v.w * ap[p];
        }
        acc.x *= inv; acc.y *= inv; acc.z *= inv; acc.w *= inv;
        *reinterpret_cast<float4*>(out + obase + c) = acc;
    }
}

// ---------------------------------------------------------------------------
extern "C" void kernel_launch(void* const* d_in, const int* in_sizes, int n_in,
                              void* d_out, int out_size)
{
    const float* x  = (const float*)d_in[0];
    const float* Wg = (const float*)d_in[1];
    const float* bg = (const float*)d_in[2];
    const float* Wk = (const float*)d_in[3];
    const float* Wq = (const float*)d_in[4];
    const float* Wv = (const float*)d_in[5];
    float* out = (float*)d_out;

    cudaFuncSetAttribute(head_k1_gate_qkv,
                         cudaFuncAttributeMaxDynamicSharedMemorySize, K1_SMEM);
    cudaFuncSetAttribute(head_k2_part,
                         cudaFuncAttributeMaxDynamicSharedMemorySize, K2_SMEM);

    head_k0_split<<<160, 256>>>(Wg, Wk, Wq, Wv);
    head_k1_gate_qkv<<<BT / 128, 512, K1_SMEM>>>(x, bg);
    head_k2_part<<<2560, 256, K2_SMEM>>>();
    head_k3_merge<<<dim3(4, 128), 256>>>(out);
}

// round 12
// speedup vs baseline: 1.3157x; 1.3157x over previous
#include <cuda_runtime.h>
#include <cuda_bf16.h>
#include <cstdint>

// Problem constants
#define BT    65536   // B*T
#define CDIM  128
#define HDIM  64
#define TSEQ  512
#define SCALE 0.088388347648318447f   // 1/sqrt(128)

// q/k scratch bf16 hi/lo in [B][T][H]; v scratch bf16 hi/lo in [B][H][T]
__device__ __nv_bfloat16 g_qhi[BT * HDIM];
__device__ __nv_bfloat16 g_qlo[BT * HDIM];
__device__ __nv_bfloat16 g_khi[BT * HDIM];
__device__ __nv_bfloat16 g_klo[BT * HDIM];
__device__ __nv_bfloat16 g_vhi[BT * HDIM];
__device__ __nv_bfloat16 g_vlo[BT * HDIM];

// pre-split weight images (k0 output), row-major [n][k], k stride 128 bf16
__device__ __nv_bfloat16 g_wgh[128 * 128];
__device__ __nv_bfloat16 g_wgl[128 * 128];
__device__ __nv_bfloat16 g_wqkvh[192 * 128];
__device__ __nv_bfloat16 g_wqkvl[192 * 128];

// ---------------------------------------------------------------------------
// helpers
// ---------------------------------------------------------------------------
__device__ __forceinline__ uint32_t smem_u32(const void* p) {
    uint32_t a;
    asm("{ .reg .u64 t; cvta.to.shared.u64 t, %1; cvt.u32.u64 %0, t; }"
        : "=r"(a) : "l"(p));
    return a;
}
__device__ __forceinline__ uint32_t pack_bf16(float lo, float hi) {
    uint32_t r;
    asm("cvt.rn.bf16x2.f32 %0, %1, %2;" : "=r"(r) : "f"(hi), "f"(lo));
    return r;
}
__device__ __forceinline__ float bf16_residual(float v) {
    return v - __bfloat162float(__float2bfloat16(v));
}
__device__ __forceinline__ void split_pack(float v0, float v1,
                                           uint32_t& hi, uint32_t& lo) {
    __nv_bfloat16 h0 = __float2bfloat16(v0);
    __nv_bfloat16 h1 = __float2bfloat16(v1);
    __nv_bfloat162 hh; hh.x = h0; hh.y = h1;
    hi = *reinterpret_cast<uint32_t*>(&hh);
    lo = pack_bf16(v0 - __bfloat162float(h0), v1 - __bfloat162float(h1));
}
__device__ __forceinline__ void mma_bf16(float* d, const uint32_t* a,
                                         const uint32_t* b) {
    asm volatile(
        "mma.sync.aligned.m16n8k16.row.col.f32.bf16.bf16.f32 "
        "{%0,%1,%2,%3}, {%4,%5,%6,%7}, {%8,%9}, {%0,%1,%2,%3};"
        : "+f"(d[0]), "+f"(d[1]), "+f"(d[2]), "+f"(d[3])
        : "r"(a[0]), "r"(a[1]), "r"(a[2]), "r"(a[3]), "r"(b[0]), "r"(b[1]));
}
__device__ __forceinline__ void cp_async16(uint32_t smem_dst, const void* gsrc) {
    asm volatile("cp.async.cg.shared.global [%0], [%1], 16;"
                 :: "r"(smem_dst), "l"(gsrc) : "memory");
}
#define CP_COMMIT() asm volatile("cp.async.commit_group;" ::: "memory")
#define CP_WAIT0()  asm volatile("cp.async.wait_group 0;" ::: "memory")

// ---------------------------------------------------------------------------
// Kernel 0: one-time weight split into bf16 hi/lo global images.
// ---------------------------------------------------------------------------
__global__ __launch_bounds__(256, 4)
void head_k0_split(const float* __restrict__ Wg,
                   const float* __restrict__ Wk,
                   const float* __restrict__ Wq,
                   const float* __restrict__ Wv)
{
    int i = blockIdx.x * 256 + threadIdx.x;
    if (i < 128 * 128) {
        int d = i >> 7, c = i & 127;
        float v = Wg[c * 128 + d];
        __nv_bfloat16 h = __float2bfloat16(v);
        g_wgh[i] = h;
        g_wgl[i] = __float2bfloat16(v - __bfloat162float(h));
    } else if (i < 128 * 128 + 192 * 128) {
        int j = i - 128 * 128;
        int e = j >> 7, c = j & 127;
        float v;
        if (e < 64)       v = Wq[c * 64 + e];
        else if (e < 128) v = Wk[c * 64 + (e - 64)];
        else              v = Wv[c * 64 + (e - 128)];
        __nv_bfloat16 h = __float2bfloat16(v);
        g_wqkvh[j] = h;
        g_wqkvl[j] = __float2bfloat16(v - __bfloat162float(h));
    }
}

// ---------------------------------------------------------------------------
// Kernel 1: gate GEMM + sigmoid-gate + QKV GEMM (bf16x3 HMMA).
// 512 threads = 16 warps = 8 row-groups x 2 N-halves; cp.async smem weights.
// (unchanged 158us-passing version)
// ---------------------------------------------------------------------------
#define K1_SMEM 174592

__global__ __launch_bounds__(512, 1)
void head_k1_gate_qkv(const float* __restrict__ x,
                      const float* __restrict__ bg)
{
    extern __shared__ char smc[];
    const uint32_t sbase = smem_u32(smc);
    __nv_bfloat16* AH = reinterpret_cast<__nv_bfloat16*>(smc);
    __nv_bfloat16* AL = reinterpret_cast<__nv_bfloat16*>(smc + 34816);
    float*         bgs = reinterpret_cast<float*>(smc + 174080);
    float*         vT  = reinterpret_cast<float*>(smc);          // overlay

    uint32_t* AHw = reinterpret_cast<uint32_t*>(AH);
    uint32_t* ALw = reinterpret_cast<uint32_t*>(AL);
    const uint32_t* BHw = reinterpret_cast<const uint32_t*>(smc + 69632);
    const uint32_t* BLw = reinterpret_cast<const uint32_t*>(smc + 121856);

    const int tid   = threadIdx.x;
    const int wid   = tid >> 5;
    const int lane  = tid & 31;
    const int g     = lane >> 2;
    const int qq    = lane & 3;
    const int q2    = qq * 2;
    const int rg    = wid >> 1;         // row group 0..7
    const int nh    = wid & 1;          // N half
    const int wbase = rg * 16;
    const int tok0  = blockIdx.x * 128;
    const int bb    = tok0 >> 9;
    const int t0    = tok0 & 511;

    // ---- issue Wg hi/lo -> B via cp.async ----
    {
        const char* wh = reinterpret_cast<const char*>(g_wgh);
        const char* wl = reinterpret_cast<const char*>(g_wgl);
        for (int i = tid; i < 2048; i += 512) {
            int row = i >> 4, ch = i & 15;
            uint32_t dof = (uint32_t)(row * 272 + ch * 16);
            cp_async16(sbase + 69632 + dof,  wh + row * 256 + ch * 16);
            cp_async16(sbase + 121856 + dof, wl + row * 256 + ch * 16);
        }
        CP_COMMIT();
    }

    // ---- load + split x -> A hi/lo (float4 vectorized) ----
    for (int i = tid; i < 4096; i += 512) {
        int t = i >> 5, c4 = (i & 31) * 4;
        float4 xv = *reinterpret_cast<const float4*>(
                        x + (size_t)(tok0 + t) * CDIM + c4);
        uint32_t h0, l0w, h1, l1w;
        split_pack(xv.x, xv.y, h0, l0w);
        split_pack(xv.z, xv.w, h1, l1w);
        int widx = t * 68 + (c4 >> 1);
        AHw[widx] = h0; AHw[widx + 1] = h1;
        ALw[widx] = l0w; ALw[widx + 1] = l1w;
    }
    if (tid < 128) bgs[tid] = bg[tid];
    CP_WAIT0();
    __syncthreads();

    // ---- phase 1: gate = x @ Wg (16 rows x 64 cols per warp) ----
    float acc[8][4];
    #pragma unroll
    for (int j = 0; j < 8; j++)
        #pragma unroll
        for (int t = 0; t < 4; t++) acc[j][t] = 0.f;

    #pragma unroll
    for (int kk = 0; kk < 8; ++kk) {
        const int kw = kk * 8 + qq;
        const int r0 = wbase + g;
        uint32_t ah[4], al[4];
        ah[0] = AHw[r0 * 68 + kw];       ah[1] = AHw[(r0 + 8) * 68 + kw];
        ah[2] = AHw[r0 * 68 + kw + 4];   ah[3] = AHw[(r0 + 8) * 68 + kw + 4];
        al[0] = ALw[r0 * 68 + kw];       al[1] = ALw[(r0 + 8) * 68 + kw];
        al[2] = ALw[r0 * 68 + kw + 4];   al[3] = ALw[(r0 + 8) * 68 + kw + 4];
        #pragma unroll
        for (int j = 0; j < 8; ++j) {
            const int n = nh * 64 + j * 8 + g;
            uint32_t bh[2] = { BHw[n * 68 + kw], BHw[n * 68 + kw + 4] };
            uint32_t bl[2] = { BLw[n * 68 + kw], BLw[n * 68 + kw + 4] };
            mma_bf16(acc[j], ah, bh);
            mma_bf16(acc[j], ah, bl);
            mma_bf16(acc[j], al, bh);
        }
    }
    __syncthreads();   // all warps done reading B (Wg)

    // ---- issue W[q|k|v] hi/lo -> B, overlapped with gate epilogue ----
    {
        const char* wh = reinterpret_cast<const char*>(g_wqkvh);
        const char* wl = reinterpret_cast<const char*>(g_wqkvl);
        for (int i = tid; i < 3072; i += 512) {
            int row = i >> 4, ch = i & 15;
            uint32_t dof = (uint32_t)(row * 272 + ch * 16);
            cp_async16(sbase + 69632 + dof,  wh + row * 256 + ch * 16);
            cp_async16(sbase + 121856 + dof, wl + row * 256 + ch * 16);
        }
        CP_COMMIT();
    }

    // ---- gate epilogue: xg = x * sigmoid(gate + bg), rewrite A (own cells) ----
    #pragma unroll
    for (int j = 0; j < 8; ++j) {
        const int col = nh * 64 + j * 8 + q2;
        #pragma unroll
        for (int hf = 0; hf < 2; ++hf) {
            const int r = wbase + g + hf * 8;
            __nv_bfloat162 hw = *reinterpret_cast<__nv_bfloat162*>(&AH[r * 136 + col]);
            __nv_bfloat162 lw = *reinterpret_cast<__nv_bfloat162*>(&AL[r * 136 + col]);
            float x0 = __bfloat162float(hw.x) + __bfloat162float(lw.x);
            float x1 = __bfloat162float(hw.y) + __bfloat162float(lw.y);
            float c0 = acc[j][hf * 2 + 0], c1 = acc[j][hf * 2 + 1];
            float g0 = 1.f / (1.f + __expf(-(c0 + bgs[col])));
            float g1 = 1.f / (1.f + __expf(-(c1 + bgs[col + 1])));
            uint32_t hiw, low;
            split_pack(x0 * g0, x1 * g1, hiw, low);
            *reinterpret_cast<uint32_t*>(&AH[r * 136 + col]) = hiw;
            *reinterpret_cast<uint32_t*>(&AL[r * 136 + col]) = low;
        }
    }
    CP_WAIT0();
    __syncthreads();

    // ---- phase 2: [q|k|v] = xg @ W (16 rows x 96 cols per warp) ----
    float acc2[12][4];
    #pragma unroll
    for (int j = 0; j < 12; j++)
        #pragma unroll
        for (int t = 0; t < 4; t++) acc2[j][t] = 0.f;

    #pragma unroll
    for (int kk = 0; kk < 8; ++kk) {
        const int kw = kk * 8 + qq;
        const int r0 = wbase + g;
        uint32_t ah[4], al[4];
        ah[0] = AHw[r0 * 68 + kw];       ah[1] = AHw[(r0 + 8) * 68 + kw];
        ah[2] = AHw[r0 * 68 + kw + 4];   ah[3] = AHw[(r0 + 8) * 68 + kw + 4];
        al[0] = ALw[r0 * 68 + kw];       al[1] = ALw[(r0 + 8) * 68 + kw];
        al[2] = ALw[r0 * 68 + kw + 4];   al[3] = ALw[(r0 + 8) * 68 + kw + 4];
        #pragma unroll
        for (int j = 0; j < 12; ++j) {
            const int n = nh * 96 + j * 8 + g;
            uint32_t bh[2] = { BHw[n * 68 + kw], BHw[n * 68 + kw + 4] };
            uint32_t bl[2] = { BLw[n * 68 + kw], BLw[n * 68 + kw + 4] };
            mma_bf16(acc2[j], ah, bh);
            mma_bf16(acc2[j], ah, bl);
            mma_bf16(acc2[j], al, bh);
        }
    }
    __syncthreads();   // all A reads done before vT overlay writes

    // ---- epilogue: route by e = nh*96 + j*8 + q2 ----
    uint32_t* gqh = reinterpret_cast<uint32_t*>(g_qhi);
    uint32_t* gql = reinterpret_cast<uint32_t*>(g_qlo);
    uint32_t* gkh = reinterpret_cast<uint32_t*>(g_khi);
    uint32_t* gkl = reinterpret_cast<uint32_t*>(g_klo);
    #pragma unroll
    for (int j = 0; j < 12; ++j) {
        const int e = nh * 96 + j * 8 + q2;
        if (e < 64) {            // q (pre-scaled)
            #pragma unroll
            for (int hf = 0; hf < 2; ++hf) {
                const int r = wbase + g + hf * 8;
                uint32_t hiw, low;
                split_pack(acc2[j][hf * 2] * SCALE, acc2[j][hf * 2 + 1] * SCALE,
                           hiw, low);
                size_t widx = (size_t)(tok0 + r) * 32 + (e >> 1);
                gqh[widx] = hiw; gql[widx] = low;
            }
        } else if (e < 128) {    // k
            const int h = e - 64;
            #pragma unroll
            for (int hf = 0; hf < 2; ++hf) {
                const int r = wbase + g + hf * 8;
                uint32_t hiw, low;
                split_pack(acc2[j][hf * 2], acc2[j][hf * 2 + 1], hiw, low);
                size_t widx = (size_t)(tok0 + r) * 32 + (h >> 1);
                gkh[widx] = hiw; gkl[widx] = low;
            }
        } else {                 // v -> vT smem (transpose)
            const int h = e - 128;
            const int r = wbase + g;
            vT[h * 132 + r]           = acc2[j][0];
            vT[(h + 1) * 132 + r]     = acc2[j][1];
            vT[h * 132 + r + 8]       = acc2[j][2];
            vT[(h + 1) * 132 + r + 8] = acc2[j][3];
        }
    }
    __syncthreads();

    // ---- v: coalesced bf16 hi/lo stores to [B][H][T] ----
    uint32_t* gvh = reinterpret_cast<uint32_t*>(g_vhi);
    uint32_t* gvl = reinterpret_cast<uint32_t*>(g_vlo);
    for (int i = tid; i < 64 * 64; i += 512) {
        int h = i >> 6, tw = i & 63;
        int t = tw * 2;
        uint32_t hiw, low;
        split_pack(vT[h * 132 + t], vT[h * 132 + t + 1], hiw, low);
        size_t widx = ((size_t)bb * 64 + h) * 256 + ((t0 + t) >> 1);
        gvh[widx] = hiw; gvl[widx] = low;
    }
}

// ---------------------------------------------------------------------------
// Kernel 2: causal flash attention, 64-q-row CTAs, 2 CTAs/SM.
// grid (8 qtiles, 128 b), 256 threads = 8 warps = 4 q-groups x 2 key-halves.
// Sequential 128-key tiles (single smem buffer); in-smem kh merge at end.
// smem words: QH 2304 @0, QL @2304, KH 4608 @4608, KL @9216,
//             VH 4352 @13824, VL @18176. total 22528 words = 90112 B.
// ---------------------------------------------------------------------------
#define K2_SMEM 90112

__global__ __launch_bounds__(256, 2)
void head_k2_attn(float* __restrict__ out)
{
    extern __shared__ char smc[];
    const uint32_t sbase = smem_u32(smc);
    uint32_t* S = reinterpret_cast<uint32_t*>(smc);
    const uint32_t* QHw = S;
    const uint32_t* QLw = S + 2304;
    const uint32_t* KHw = S + 4608;
    const uint32_t* KLw = S + 9216;
    const uint32_t* VHw = S + 13824;
    const uint32_t* VLw = S + 18176;

    const int tid   = threadIdx.x;
    const int wid   = tid >> 5;
    const int lane  = tid & 31;
    const int g     = lane >> 2;
    const int qq    = lane & 3;
    const int q2    = qq * 2;
    const int qg    = wid & 3;          // q group 0..3 (16 rows each)
    const int kh    = wid >> 2;         // key half
    const int wbase = qg * 16;
    const int qt    = blockIdx.x;       // 0..7 (64-row q tiles)
    const int b     = blockIdx.y;
    const int q0    = qt * 64;
    const int nt    = qt / 2 + 1;       // number of 128-key tiles

    const uint32_t* gqh = reinterpret_cast<const uint32_t*>(g_qhi);
    const uint32_t* gql = reinterpret_cast<const uint32_t*>(g_qlo);
    const uint32_t* gkh = reinterpret_cast<const uint32_t*>(g_khi);
    const uint32_t* gkl = reinterpret_cast<const uint32_t*>(g_klo);
    const uint32_t* gvh = reinterpret_cast<const uint32_t*>(g_vhi);
    const uint32_t* gvl = reinterpret_cast<const uint32_t*>(g_vlo);

    // ---- issue Q (64 rows) ----
    {
        size_t qbase = ((size_t)b * 512 + q0) * 32;
        for (int i = tid; i < 512; i += 256) {
            int row = i >> 3, cw = (i & 7) * 4;
            uint32_t dof = (uint32_t)(row * 36 + cw) * 4;
            cp_async16(sbase + dof,            gqh + qbase + row * 32 + cw);
            cp_async16(sbase + 2304 * 4 + dof, gql + qbase + row * 32 + cw);
        }
    }

    float o[8][4];
    #pragma unroll
    for (int j = 0; j < 8; j++)
        #pragma unroll
        for (int t = 0; t < 4; t++) o[j][t] = 0.f;
    float m0 = -1e30f, m1 = -1e30f, l0 = 0.f, l1 = 0.f;

    for (int jt = 0; jt < nt; ++jt) {
        if (jt) __syncthreads();        // prev tile fully consumed

        // ---- issue K/V tile jt (128 keys) ----
        {
            size_t kbase = ((size_t)b * 512 + jt * 128) * 32;
            for (int i = tid; i < 1024; i += 256) {
                int row = i >> 3, cw = (i & 7) * 4;
                uint32_t dof = (uint32_t)(4608 + row * 36 + cw) * 4;
                cp_async16(sbase + dof,            gkh + kbase + row * 32 + cw);
                cp_async16(sbase + dof + 4608 * 4, gkl + kbase + row * 32 + cw);
            }
            size_t vbase = (size_t)b * 64 * 256 + jt * 64;
            for (int i = tid; i < 1024; i += 256) {
                int h = i >> 4, cw = (i & 15) * 4;
                uint32_t dof = (uint32_t)(13824 + h * 68 + cw) * 4;
                cp_async16(sbase + dof,            gvh + vbase + h * 256 + cw);
                cp_async16(sbase + dof + 4352 * 4, gvl + vbase + h * 256 + cw);
            }
            CP_COMMIT();
        }
        CP_WAIT0();
        __syncthreads();

        // skip warp-tiles whose keys all exceed this warp's max row
        if (jt * 128 + kh * 64 > q0 + wbase + 15) continue;

        // ---- S = Q K^T (16 rows x 64 keys per warp) ----
        float s[8][4];
        #pragma unroll
        for (int j = 0; j < 8; j++)
            #pragma unroll
            for (int t = 0; t < 4; t++) s[j][t] = 0.f;

        #pragma unroll
        for (int kk = 0; kk < 4; ++kk) {
            const int kw = kk * 8 + qq;
            const int r0w = wbase + g;
            uint32_t qh[4], ql[4];
            qh[0] = QHw[r0w * 36 + kw];     qh[1] = QHw[(r0w + 8) * 36 + kw];
            qh[2] = QHw[r0w * 36 + kw + 4]; qh[3] = QHw[(r0w + 8) * 36 + kw + 4];
            ql[0] = QLw[r0w * 36 + kw];     ql[1] = QLw[(r0w + 8) * 36 + kw];
            ql[2] = QLw[r0w * 36 + kw + 4]; ql[3] = QLw[(r0w + 8) * 36 + kw + 4];
            #pragma unroll
            for (int j = 0; j < 8; ++j) {
                const int n = kh * 64 + j * 8 + g;
                uint32_t bh[2] = { KHw[n * 36 + kw], KHw[n * 36 + kw + 4] };
                uint32_t bl[2] = { KLw[n * 36 + kw], KLw[n * 36 + kw + 4] };
                mma_bf16(s[j], qh, bh);
                mma_bf16(s[j], qh, bl);
                mma_bf16(s[j], ql, bh);
            }
        }

        // ---- causal mask (only the last tile can straddle the diagonal) ----
        if (jt == nt - 1) {
            const int r0 = q0 + wbase + g;
            const int cb = jt * 128 + kh * 64;
            #pragma unroll
            for (int j = 0; j < 8; ++j) {
                const int c0 = cb + j * 8 + q2;
                if (c0     > r0)     s[j][0] = -1e30f;
                if (c0 + 1 > r0)     s[j][1] = -1e30f;
                if (c0     > r0 + 8) s[j][2] = -1e30f;
                if (c0 + 1 > r0 + 8) s[j][3] = -1e30f;
            }
        }

        // ---- online softmax (quad shuffles per row) ----
        float mx0 = -1e30f, mx1 = -1e30f;
        #pragma unroll
        for (int j = 0; j < 8; ++j) {
            mx0 = fmaxf(mx0, fmaxf(s[j][0], s[j][1]));
            mx1 = fmaxf(mx1, fmaxf(s[j][2], s[j][3]));
        }
        mx0 = fmaxf(mx0, __shfl_xor_sync(0xffffffffu, mx0, 1));
        mx0 = fmaxf(mx0, __shfl_xor_sync(0xffffffffu, mx0, 2));
        mx1 = fmaxf(mx1, __shfl_xor_sync(0xffffffffu, mx1, 1));
        mx1 = fmaxf(mx1, __shfl_xor_sync(0xffffffffu, mx1, 2));
        const float mn0 = fmaxf(m0, mx0), mn1 = fmaxf(m1, mx1);
        const float a0 = __expf(m0 - mn0), a1 = __expf(m1 - mn1);
        m0 = mn0; m1 = mn1;
        l0 *= a0; l1 *= a1;
        #pragma unroll
        for (int j = 0; j < 8; ++j) {
            o[j][0] *= a0; o[j][1] *= a0; o[j][2] *= a1; o[j][3] *= a1;
        }
        float s0 = 0.f, s1 = 0.f;
        #pragma unroll
        for (int j = 0; j < 8; ++j) {
            s[j][0] = __expf(s[j][0] - mn0); s0 += s[j][0];
            s[j][1] = __expf(s[j][1] - mn0); s0 += s[j][1];
            s[j][2] = __expf(s[j][2] - mn1); s1 += s[j][2];
            s[j][3] = __expf(s[j][3] - mn1); s1 += s[j][3];
        }
        s0 += __shfl_xor_sync(0xffffffffu, s0, 1);
        s0 += __shfl_xor_sync(0xffffffffu, s0, 2);
        s1 += __shfl_xor_sync(0xffffffffu, s1, 1);
        s1 += __shfl_xor_sync(0xffffffffu, s1, 2);
        l0 += s0; l1 += s1;

        // ---- O += P @ V over this warp's 64 keys ----
        #pragma unroll
        for (int kk2 = 0; kk2 < 4; ++kk2) {
            const int j0 = kk2 * 2, j1 = j0 + 1;
            uint32_t ah[4], al[4];
            ah[0] = pack_bf16(s[j0][0], s[j0][1]);
            ah[1] = pack_bf16(s[j0][2], s[j0][3]);
            ah[2] = pack_bf16(s[j1][0], s[j1][1]);
            ah[3] = pack_bf16(s[j1][2], s[j1][3]);
            al[0] = pack_bf16(bf16_residual(s[j0][0]), bf16_residual(s[j0][1]));
            al[1] = pack_bf16(bf16_residual(s[j0][2]), bf16_residual(s[j0][3]));
            al[2] = pack_bf16(bf16_residual(s[j1][0]), bf16_residual(s[j1][1]));
            al[3] = pack_bf16(bf16_residual(s[j1][2]), bf16_residual(s[j1][3]));
            const int kwv = kh * 32 + kk2 * 8 + qq;
            #pragma unroll
            for (int jn = 0; jn < 8; ++jn) {
                const int hN = jn * 8 + g;
                uint32_t vh[2] = { VHw[hN * 68 + kwv], VHw[hN * 68 + kwv + 4] };
                uint32_t vl[2] = { VLw[hN * 68 + kwv], VLw[hN * 68 + kwv + 4] };
                mma_bf16(o[jn], ah, vh);
                mma_bf16(o[jn], ah, vl);
                mma_bf16(o[jn], al, vh);
            }
        }
    }

    // ---- merge key-halves through smem (overlay K region), write out ----
    __syncthreads();                          // everyone done with K/V buffer
    float* oB = reinterpret_cast<float*>(S + 4608);   // 64 x 68 over KH
    float* mB = reinterpret_cast<float*>(S + 9216);   // 64 over KL
    float* lB = mB + 64;

    if (kh == 1) {
        #pragma unroll
        for (int j = 0; j < 8; ++j) {
            const int h = j * 8 + q2;
            oB[(wbase + g) * 68 + h]         = o[j][0];
            oB[(wbase + g) * 68 + h + 1]     = o[j][1];
            oB[(wbase + 8 + g) * 68 + h]     = o[j][2];
            oB[(wbase + 8 + g) * 68 + h + 1] = o[j][3];
        }
        if (qq == 0) {
            mB[wbase + g] = m0;     lB[wbase + g] = l0;
            mB[wbase + 8 + g] = m1; lB[wbase + 8 + g] = l1;
        }
    }
    __syncthreads();

    if (kh == 0) {
        const int r0 = wbase + g, r1 = r0 + 8;
        const float mb0 = mB[r0], mb1 = mB[r1];
        const float mF0 = fmaxf(m0, mb0), mF1 = fmaxf(m1, mb1);
        const float aA0 = __expf(m0 - mF0), aB0 = __expf(mb0 - mF0);
        const float aA1 = __expf(m1 - mF1), aB1 = __expf(mb1 - mF1);
        const float i0 = 1.f / (l0 * aA0 + lB[r0] * aB0);
        const float i1 = 1.f / (l1 * aA1 + lB[r1] * aB1);
        const int gr0 = q0 + r0;
        const size_t ob = (size_t)b * TSEQ * HDIM;
        #pragma unroll
        for (int jn = 0; jn < 8; ++jn) {
            const int h = jn * 8 + q2;
            float2 v0, v1;
            v0.x = (o[jn][0] * aA0 + oB[r0 * 68 + h]     * aB0) * i0;
            v0.y = (o[jn][1] * aA0 + oB[r0 * 68 + h + 1] * aB0) * i0;
            v1.x = (o[jn][2] * aA1 + oB[r1 * 68 + h]     * aB1) * i1;
            v1.y = (o[jn][3] * aA1 + oB[r1 * 68 + h + 1] * aB1) * i1;
            *reinterpret_cast<float2*>(out + ob + (size_t)gr0 * 64 + h)       = v0;
            *reinterpret_cast<float2*>(out + ob + (size_t)(gr0 + 8) * 64 + h) = v1;
        }
    }
}

// ---------------------------------------------------------------------------
extern "C" void kernel_launch(void* const* d_in, const int* in_sizes, int n_in,
                              void* d_out, int out_size)
{
    const float* x  = (const float*)d_in[0];
    const float* Wg = (const float*)d_in[1];
    const float* bg = (const float*)d_in[2];
    const float* Wk = (const float*)d_in[3];
    const float* Wq = (const float*)d_in[4];
    const float* Wv = (const float*)d_in[5];
    float* out = (float*)d_out;

    cudaFuncSetAttribute(head_k1_gate_qkv,
                         cudaFuncAttributeMaxDynamicSharedMemorySize, K1_SMEM);
    cudaFuncSetAttribute(head_k2_attn,
                         cudaFuncAttributeMaxDynamicSharedMemorySize, K2_SMEM);

    head_k0_split<<<160, 256>>>(Wg, Wk, Wq, Wv);
    head_k1_gate_qkv<<<BT / 128, 512, K1_SMEM>>>(x, bg);
    head_k2_attn<<<dim3(8, 128), 256, K2_SMEM>>>(out);
}

// round 13
// speedup vs baseline: 1.4106x; 1.0722x over previous
#include <cuda_runtime.h>
#include <cuda_bf16.h>
#include <cstdint>

// Problem constants
#define BT    65536   // B*T
#define CDIM  128
#define HDIM  64
#define TSEQ  512
#define SCALE 0.088388347648318447f   // 1/sqrt(128)

// q/k scratch bf16 hi/lo in [B][T][H]; v scratch bf16 hi/lo in [B][H][T]
__device__ __nv_bfloat16 g_qhi[BT * HDIM];
__device__ __nv_bfloat16 g_qlo[BT * HDIM];
__device__ __nv_bfloat16 g_khi[BT * HDIM];
__device__ __nv_bfloat16 g_klo[BT * HDIM];
__device__ __nv_bfloat16 g_vhi[BT * HDIM];
__device__ __nv_bfloat16 g_vlo[BT * HDIM];

// pre-split weight images (k0 output), row-major [n][k], k stride 128 bf16
__device__ __nv_bfloat16 g_wgh[128 * 128];
__device__ __nv_bfloat16 g_wgl[128 * 128];
__device__ __nv_bfloat16 g_wqkvh[192 * 128];
__device__ __nv_bfloat16 g_wqkvl[192 * 128];

// ---------------------------------------------------------------------------
// helpers
// ---------------------------------------------------------------------------
__device__ __forceinline__ uint32_t smem_u32(const void* p) {
    uint32_t a;
    asm("{ .reg .u64 t; cvta.to.shared.u64 t, %1; cvt.u32.u64 %0, t; }"
        : "=r"(a) : "l"(p));
    return a;
}
__device__ __forceinline__ uint32_t pack_bf16(float lo, float hi) {
    uint32_t r;
    asm("cvt.rn.bf16x2.f32 %0, %1, %2;" : "=r"(r) : "f"(hi), "f"(lo));
    return r;
}
__device__ __forceinline__ float bf16_residual(float v) {
    return v - __bfloat162float(__float2bfloat16(v));
}
__device__ __forceinline__ void split_pack(float v0, float v1,
                                           uint32_t& hi, uint32_t& lo) {
    __nv_bfloat16 h0 = __float2bfloat16(v0);
    __nv_bfloat16 h1 = __float2bfloat16(v1);
    __nv_bfloat162 hh; hh.x = h0; hh.y = h1;
    hi = *reinterpret_cast<uint32_t*>(&hh);
    lo = pack_bf16(v0 - __bfloat162float(h0), v1 - __bfloat162float(h1));
}
__device__ __forceinline__ void mma_bf16(float* d, const uint32_t* a,
                                         const uint32_t* b) {
    asm volatile(
        "mma.sync.aligned.m16n8k16.row.col.f32.bf16.bf16.f32 "
        "{%0,%1,%2,%3}, {%4,%5,%6,%7}, {%8,%9}, {%0,%1,%2,%3};"
        : "+f"(d[0]), "+f"(d[1]), "+f"(d[2]), "+f"(d[3])
        : "r"(a[0]), "r"(a[1]), "r"(a[2]), "r"(a[3]), "r"(b[0]), "r"(b[1]));
}
__device__ __forceinline__ void cp_async16(uint32_t smem_dst, const void* gsrc) {
    asm volatile("cp.async.cg.shared.global [%0], [%1], 16;"
                 :: "r"(smem_dst), "l"(gsrc) : "memory");
}
#define CP_COMMIT() asm volatile("cp.async.commit_group;" ::: "memory")
#define CP_WAIT0()  asm volatile("cp.async.wait_group 0;" ::: "memory")
#define CP_WAIT1()  asm volatile("cp.async.wait_group 1;" ::: "memory")

// ---------------------------------------------------------------------------
// Kernel 0: one-time weight split into bf16 hi/lo global images.
// ---------------------------------------------------------------------------
__global__ __launch_bounds__(256, 4)
void head_k0_split(const float* __restrict__ Wg,
                   const float* __restrict__ Wk,
                   const float* __restrict__ Wq,
                   const float* __restrict__ Wv)
{
    int i = blockIdx.x * 256 + threadIdx.x;
    if (i < 128 * 128) {
        int d = i >> 7, c = i & 127;
        float v = Wg[c * 128 + d];
        __nv_bfloat16 h = __float2bfloat16(v);
        g_wgh[i] = h;
        g_wgl[i] = __float2bfloat16(v - __bfloat162float(h));
    } else if (i < 128 * 128 + 192 * 128) {
        int j = i - 128 * 128;
        int e = j >> 7, c = j & 127;
        float v;
        if (e < 64)       v = Wq[c * 64 + e];
        else if (e < 128) v = Wk[c * 64 + (e - 64)];
        else              v = Wv[c * 64 + (e - 128)];
        __nv_bfloat16 h = __float2bfloat16(v);
        g_wqkvh[j] = h;
        g_wqkvl[j] = __float2bfloat16(v - __bfloat162float(h));
    }
}

// ---------------------------------------------------------------------------
// Kernel 1: gate GEMM + sigmoid-gate + QKV GEMM (bf16x3 HMMA).
// 64-token CTAs, 256 threads = 8 warps = 4 row-groups(16 rows) x 2 N-halves.
// Weights stream as five 64-row chunks through double-buffered B0/B1.
// smem bytes: AH @0 (17408), AL @17408, B0H @34816, B0L @52224,
//             B1H @69632, B1L @87040, bg @104448. total 104960. 2 CTAs/SM.
// ---------------------------------------------------------------------------
#define K1_SMEM 104960

// one 64xN-chunk bf16x3 GEMM contribution: 16 rows x 32 cols per warp
__device__ __forceinline__ void gemm_chunk(const uint32_t* AHw, const uint32_t* ALw,
                                           const uint32_t* BHw, const uint32_t* BLw,
                                           int wbase, int g, int qq, int nh,
                                           float acc[4][4]) {
    #pragma unroll
    for (int kk = 0; kk < 8; ++kk) {
        const int kw = kk * 8 + qq;
        const int r0 = wbase + g;
        uint32_t ah[4], al[4];
        ah[0] = AHw[r0 * 68 + kw];       ah[1] = AHw[(r0 + 8) * 68 + kw];
        ah[2] = AHw[r0 * 68 + kw + 4];   ah[3] = AHw[(r0 + 8) * 68 + kw + 4];
        al[0] = ALw[r0 * 68 + kw];       al[1] = ALw[(r0 + 8) * 68 + kw];
        al[2] = ALw[r0 * 68 + kw + 4];   al[3] = ALw[(r0 + 8) * 68 + kw + 4];
        #pragma unroll
        for (int j = 0; j < 4; ++j) {
            const int n = nh * 32 + j * 8 + g;
            uint32_t bh[2] = { BHw[n * 68 + kw], BHw[n * 68 + kw + 4] };
            uint32_t bl[2] = { BLw[n * 68 + kw], BLw[n * 68 + kw + 4] };
            mma_bf16(acc[j], ah, bh);
            mma_bf16(acc[j], ah, bl);
            mma_bf16(acc[j], al, bh);
        }
    }
}

__global__ __launch_bounds__(256, 2)
void head_k1_gate_qkv(const float* __restrict__ x,
                      const float* __restrict__ bg)
{
    extern __shared__ char smc[];
    const uint32_t sbase = smem_u32(smc);
    __nv_bfloat16* AH = reinterpret_cast<__nv_bfloat16*>(smc);
    __nv_bfloat16* AL = reinterpret_cast<__nv_bfloat16*>(smc + 17408);
    float*         bgs = reinterpret_cast<float*>(smc + 104448);
    float*         vT  = reinterpret_cast<float*>(smc);          // overlay

    uint32_t* AHw = reinterpret_cast<uint32_t*>(AH);
    uint32_t* ALw = reinterpret_cast<uint32_t*>(AL);
    const uint32_t* B0H = reinterpret_cast<const uint32_t*>(smc + 34816);
    const uint32_t* B0L = reinterpret_cast<const uint32_t*>(smc + 52224);
    const uint32_t* B1H = reinterpret_cast<const uint32_t*>(smc + 69632);
    const uint32_t* B1L = reinterpret_cast<const uint32_t*>(smc + 87040);

    const int tid   = threadIdx.x;
    const int wid   = tid >> 5;
    const int lane  = tid & 31;
    const int g     = lane >> 2;
    const int qq    = lane & 3;
    const int q2    = qq * 2;
    const int rg    = wid >> 1;         // row group 0..3
    const int nh    = wid & 1;          // N half within a chunk
    const int wbase = rg * 16;
    const int tok0  = blockIdx.x * 64;
    const int bb    = tok0 >> 9;
    const int t0    = tok0 & 511;

    // chunk issue helper: 64 weight rows (hi+lo) -> one B buffer
    auto issue_chunk = [&](uint32_t dstH, uint32_t dstL,
                           const char* srcH, const char* srcL) {
        for (int i = tid; i < 1024; i += 256) {
            int row = i >> 4, ch = i & 15;
            uint32_t dof = (uint32_t)(row * 272 + ch * 16);
            cp_async16(sbase + dstH + dof, srcH + row * 256 + ch * 16);
            cp_async16(sbase + dstL + dof, srcL + row * 256 + ch * 16);
        }
        CP_COMMIT();
    };

    // G0: Wg rows 0-63 -> B0 ; G1: Wg rows 64-127 -> B1
    issue_chunk(34816, 52224, (const char*)g_wgh, (const char*)g_wgl);
    issue_chunk(69632, 87040, (const char*)g_wgh + 64 * 256,
                              (const char*)g_wgl + 64 * 256);

    // ---- load + split x -> A hi/lo (float4 vectorized), overlaps weights ----
    for (int i = tid; i < 2048; i += 256) {
        int t = i >> 5, c4 = (i & 31) * 4;
        float4 xv = *reinterpret_cast<const float4*>(
                        x + (size_t)(tok0 + t) * CDIM + c4);
        uint32_t h0, l0w, h1, l1w;
        split_pack(xv.x, xv.y, h0, l0w);
        split_pack(xv.z, xv.w, h1, l1w);
        int widx = t * 68 + (c4 >> 1);
        AHw[widx] = h0; AHw[widx + 1] = h1;
        ALw[widx] = l0w; ALw[widx + 1] = l1w;
    }
    if (tid < 128) bgs[tid] = bg[tid];

    float gA[4][4], gB[4][4];
    #pragma unroll
    for (int j = 0; j < 4; j++)
        #pragma unroll
        for (int t = 0; t < 4; t++) { gA[j][t] = 0.f; gB[j][t] = 0.f; }

    // ---- chunk0: gate cols 0..63 (B0) ----
    CP_WAIT1();
    __syncthreads();
    gemm_chunk(AHw, ALw, B0H, B0L, wbase, g, qq, nh, gA);
    __syncthreads();                                   // B0 free
    // G2: Wqkv rows 0-63 (q cols) -> B0
    issue_chunk(34816, 52224, (const char*)g_wqkvh, (const char*)g_wqkvl);

    // ---- chunk1: gate cols 64..127 (B1) ----
    CP_WAIT1();
    __syncthreads();
    gemm_chunk(AHw, ALw, B1H, B1L, wbase, g, qq, nh, gB);

    // ---- gate epilogue: xg = x * sigmoid(gate + bg), rewrite A ----
    #pragma unroll
    for (int ck = 0; ck < 2; ++ck) {
        float (*acc)[4] = ck ? gB : gA;
        #pragma unroll
        for (int j = 0; j < 4; ++j) {
            const int col = ck * 64 + nh * 32 + j * 8 + q2;
            #pragma unroll
            for (int hf = 0; hf < 2; ++hf) {
                const int r = wbase + g + hf * 8;
                __nv_bfloat162 hw = *reinterpret_cast<__nv_bfloat162*>(&AH[r * 136 + col]);
                __nv_bfloat162 lw = *reinterpret_cast<__nv_bfloat162*>(&AL[r * 136 + col]);
                float x0 = __bfloat162float(hw.x) + __bfloat162float(lw.x);
                float x1 = __bfloat162float(hw.y) + __bfloat162float(lw.y);
                float c0 = acc[j][hf * 2 + 0], c1 = acc[j][hf * 2 + 1];
                float g0 = 1.f / (1.f + __expf(-(c0 + bgs[col])));
                float g1 = 1.f / (1.f + __expf(-(c1 + bgs[col + 1])));
                uint32_t hiw, low;
                split_pack(x0 * g0, x1 * g1, hiw, low);
                *reinterpret_cast<uint32_t*>(&AH[r * 136 + col]) = hiw;
                *reinterpret_cast<uint32_t*>(&AL[r * 136 + col]) = low;
            }
        }
    }
    __syncthreads();                                   // xg visible; B1 free
    // G3: Wqkv rows 64-127 (k cols) -> B1
    issue_chunk(69632, 87040, (const char*)g_wqkvh + 64 * 256,
                              (const char*)g_wqkvl + 64 * 256);

    uint32_t* gqh = reinterpret_cast<uint32_t*>(g_qhi);
    uint32_t* gql = reinterpret_cast<uint32_t*>(g_qlo);
    uint32_t* gkh = reinterpret_cast<uint32_t*>(g_khi);
    uint32_t* gkl = reinterpret_cast<uint32_t*>(g_klo);

    // ---- chunk2: q cols 0..63 (B0) ----
    {
        float acc[4][4];
        #pragma unroll
        for (int j = 0; j < 4; j++)
            #pragma unroll
            for (int t = 0; t < 4; t++) acc[j][t] = 0.f;
        CP_WAIT1();
        __syncthreads();
        gemm_chunk(AHw, ALw, B0H, B0L, wbase, g, qq, nh, acc);
        #pragma unroll
        for (int j = 0; j < 4; ++j) {
            const int h = nh * 32 + j * 8 + q2;
            #pragma unroll
            for (int hf = 0; hf < 2; ++hf) {
                const int r = wbase + g + hf * 8;
                uint32_t hiw, low;
                split_pack(acc[j][hf * 2] * SCALE, acc[j][hf * 2 + 1] * SCALE,
                           hiw, low);
                size_t widx = (size_t)(tok0 + r) * 32 + (h >> 1);
                gqh[widx] = hiw; gql[widx] = low;
            }
        }
        __syncthreads();                               // B0 free
    }
    // G4: Wqkv rows 128-191 (v cols) -> B0
    issue_chunk(34816, 52224, (const char*)g_wqkvh + 128 * 256,
                              (const char*)g_wqkvl + 128 * 256);

    // ---- chunk3: k cols 0..63 (B1) ----
    {
        float acc[4][4];
        #pragma unroll
        for (int j = 0; j < 4; j++)
            #pragma unroll
            for (int t = 0; t < 4; t++) acc[j][t] = 0.f;
        CP_WAIT1();
        __syncthreads();
        gemm_chunk(AHw, ALw, B1H, B1L, wbase, g, qq, nh, acc);
        #pragma unroll
        for (int j = 0; j < 4; ++j) {
            const int h = nh * 32 + j * 8 + q2;
            #pragma unroll
            for (int hf = 0; hf < 2; ++hf) {
                const int r = wbase + g + hf * 8;
                uint32_t hiw, low;
                split_pack(acc[j][hf * 2], acc[j][hf * 2 + 1], hiw, low);
                size_t widx = (size_t)(tok0 + r) * 32 + (h >> 1);
                gkh[widx] = hiw; gkl[widx] = low;
            }
        }
    }

    // ---- chunk4: v cols 0..63 (B0) ----
    {
        float acc[4][4];
        #pragma unroll
        for (int j = 0; j < 4; j++)
            #pragma unroll
            for (int t = 0; t < 4; t++) acc[j][t] = 0.f;
        CP_WAIT0();
        __syncthreads();
        gemm_chunk(AHw, ALw, B0H, B0L, wbase, g, qq, nh, acc);
        __syncthreads();                               // A free for vT overlay
        #pragma unroll
        for (int j = 0; j < 4; ++j) {
            const int h = nh * 32 + j * 8 + q2;        // 0..63
            const int r = wbase + g;
            vT[h * 68 + r]           = acc[j][0];
            vT[(h + 1) * 68 + r]     = acc[j][1];
            vT[h * 68 + r + 8]       = acc[j][2];
            vT[(h + 1) * 68 + r + 8] = acc[j][3];
        }
    }
    __syncthreads();

    // ---- v: coalesced bf16 hi/lo stores to [B][H][T] ----
    uint32_t* gvh = reinterpret_cast<uint32_t*>(g_vhi);
    uint32_t* gvl = reinterpret_cast<uint32_t*>(g_vlo);
    for (int i = tid; i < 64 * 32; i += 256) {
        int h = i >> 5, tw = i & 31;
        int t = tw * 2;
        uint32_t hiw, low;
        split_pack(vT[h * 68 + t], vT[h * 68 + t + 1], hiw, low);
        size_t widx = ((size_t)bb * 64 + h) * 256 + ((t0 + t) >> 1);
        gvh[widx] = hiw; gvl[widx] = low;
    }
}

// ---------------------------------------------------------------------------
// Kernel 2: causal flash attention, 64-q-row CTAs, 2 CTAs/SM. (R12 version)
// grid (8 qtiles, 128 b), 256 threads = 8 warps = 4 q-groups x 2 key-halves.
// smem words: QH 2304 @0, QL @2304, KH 4608 @4608, KL @9216,
//             VH 4352 @13824, VL @18176. total 22528 words = 90112 B.
// ---------------------------------------------------------------------------
#define K2_SMEM 90112

__global__ __launch_bounds__(256, 2)
void head_k2_attn(float* __restrict__ out)
{
    extern __shared__ char smc[];
    const uint32_t sbase = smem_u32(smc);
    uint32_t* S = reinterpret_cast<uint32_t*>(smc);
    const uint32_t* QHw = S;
    const uint32_t* QLw = S + 2304;
    const uint32_t* KHw = S + 4608;
    const uint32_t* KLw = S + 9216;
    const uint32_t* VHw = S + 13824;
    const uint32_t* VLw = S + 18176;

    const int tid   = threadIdx.x;
    const int wid   = tid >> 5;
    const int lane  = tid & 31;
    const int g     = lane >> 2;
    const int qq    = lane & 3;
    const int q2    = qq * 2;
    const int qg    = wid & 3;          // q group 0..3 (16 rows each)
    const int kh    = wid >> 2;         // key half
    const int wbase = qg * 16;
    const int qt    = blockIdx.x;       // 0..7 (64-row q tiles)
    const int b     = blockIdx.y;
    const int q0    = qt * 64;
    const int nt    = qt / 2 + 1;       // number of 128-key tiles

    const uint32_t* gqh = reinterpret_cast<const uint32_t*>(g_qhi);
    const uint32_t* gql = reinterpret_cast<const uint32_t*>(g_qlo);
    const uint32_t* gkh = reinterpret_cast<const uint32_t*>(g_khi);
    const uint32_t* gkl = reinterpret_cast<const uint32_t*>(g_klo);
    const uint32_t* gvh = reinterpret_cast<const uint32_t*>(g_vhi);
    const uint32_t* gvl = reinterpret_cast<const uint32_t*>(g_vlo);

    // ---- issue Q (64 rows) ----
    {
        size_t qbase = ((size_t)b * 512 + q0) * 32;
        for (int i = tid; i < 512; i += 256) {
            int row = i >> 3, cw = (i & 7) * 4;
            uint32_t dof = (uint32_t)(row * 36 + cw) * 4;
            cp_async16(sbase + dof,            gqh + qbase + row * 32 + cw);
            cp_async16(sbase + 2304 * 4 + dof, gql + qbase + row * 32 + cw);
        }
    }

    float o[8][4];
    #pragma unroll
    for (int j = 0; j < 8; j++)
        #pragma unroll
        for (int t = 0; t < 4; t++) o[j][t] = 0.f;
    float m0 = -1e30f, m1 = -1e30f, l0 = 0.f, l1 = 0.f;

    for (int jt = 0; jt < nt; ++jt) {
        if (jt) __syncthreads();        // prev tile fully consumed

        // ---- issue K/V tile jt (128 keys) ----
        {
            size_t kbase = ((size_t)b * 512 + jt * 128) * 32;
            for (int i = tid; i < 1024; i += 256) {
                int row = i >> 3, cw = (i & 7) * 4;
                uint32_t dof = (uint32_t)(4608 + row * 36 + cw) * 4;
                cp_async16(sbase + dof,            gkh + kbase + row * 32 + cw);
                cp_async16(sbase + dof + 4608 * 4, gkl + kbase + row * 32 + cw);
            }
            size_t vbase = (size_t)b * 64 * 256 + jt * 64;
            for (int i = tid; i < 1024; i += 256) {
                int h = i >> 4, cw = (i & 15) * 4;
                uint32_t dof = (uint32_t)(13824 + h * 68 + cw) * 4;
                cp_async16(sbase + dof,            gvh + vbase + h * 256 + cw);
                cp_async16(sbase + dof + 4352 * 4, gvl + vbase + h * 256 + cw);
            }
            CP_COMMIT();
        }
        CP_WAIT0();
        __syncthreads();

        // skip warp-tiles whose keys all exceed this warp's max row
        if (jt * 128 + kh * 64 > q0 + wbase + 15) continue;

        // ---- S = Q K^T (16 rows x 64 keys per warp) ----
        float s[8][4];
        #pragma unroll
        for (int j = 0; j < 8; j++)
            #pragma unroll
            for (int t = 0; t < 4; t++) s[j][t] = 0.f;

        #pragma unroll
        for (int kk = 0; kk < 4; ++kk) {
            const int kw = kk * 8 + qq;
            const int r0w = wbase + g;
            uint32_t qh[4], ql[4];
            qh[0] = QHw[r0w * 36 + kw];     qh[1] = QHw[(r0w + 8) * 36 + kw];
            qh[2] = QHw[r0w * 36 + kw + 4]; qh[3] = QHw[(r0w + 8) * 36 + kw + 4];
            ql[0] = QLw[r0w * 36 + kw];     ql[1] = QLw[(r0w + 8) * 36 + kw];
            ql[2] = QLw[r0w * 36 + kw + 4]; ql[3] = QLw[(r0w + 8) * 36 + kw + 4];
            #pragma unroll
            for (int j = 0; j < 8; ++j) {
                const int n = kh * 64 + j * 8 + g;
                uint32_t bh[2] = { KHw[n * 36 + kw], KHw[n * 36 + kw + 4] };
                uint32_t bl[2] = { KLw[n * 36 + kw], KLw[n * 36 + kw + 4] };
                mma_bf16(s[j], qh, bh);
                mma_bf16(s[j], qh, bl);
                mma_bf16(s[j], ql, bh);
            }
        }

        // ---- causal mask (only the last tile can straddle the diagonal) ----
        if (jt == nt - 1) {
            const int r0 = q0 + wbase + g;
            const int cb = jt * 128 + kh * 64;
            #pragma unroll
            for (int j = 0; j < 8; ++j) {
                const int c0 = cb + j * 8 + q2;
                if (c0     > r0)     s[j][0] = -1e30f;
                if (c0 + 1 > r0)     s[j][1] = -1e30f;
                if (c0     > r0 + 8) s[j][2] = -1e30f;
                if (c0 + 1 > r0 + 8) s[j][3] = -1e30f;
            }
        }

        // ---- online softmax (quad shuffles per row) ----
        float mx0 = -1e30f, mx1 = -1e30f;
        #pragma unroll
        for (int j = 0; j < 8; ++j) {
            mx0 = fmaxf(mx0, fmaxf(s[j][0], s[j][1]));
            mx1 = fmaxf(mx1, fmaxf(s[j][2], s[j][3]));
        }
        mx0 = fmaxf(mx0, __shfl_xor_sync(0xffffffffu, mx0, 1));
        mx0 = fmaxf(mx0, __shfl_xor_sync(0xffffffffu, mx0, 2));
        mx1 = fmaxf(mx1, __shfl_xor_sync(0xffffffffu, mx1, 1));
        mx1 = fmaxf(mx1, __shfl_xor_sync(0xffffffffu, mx1, 2));
        const float mn0 = fmaxf(m0, mx0), mn1 = fmaxf(m1, mx1);
        const float a0 = __expf(m0 - mn0), a1 = __expf(m1 - mn1);
        m0 = mn0; m1 = mn1;
        l0 *= a0; l1 *= a1;
        #pragma unroll
        for (int j = 0; j < 8; ++j) {
            o[j][0] *= a0; o[j][1] *= a0; o[j][2] *= a1; o[j][3] *= a1;
        }
        float s0 = 0.f, s1 = 0.f;
        #pragma unroll
        for (int j = 0; j < 8; ++j) {
            s[j][0] = __expf(s[j][0] - mn0); s0 += s[j][0];
            s[j][1] = __expf(s[j][1] - mn0); s0 += s[j][1];
            s[j][2] = __expf(s[j][2] - mn1); s1 += s[j][2];
            s[j][3] = __expf(s[j][3] - mn1); s1 += s[j][3];
        }
        s0 += __shfl_xor_sync(0xffffffffu, s0, 1);
        s0 += __shfl_xor_sync(0xffffffffu, s0, 2);
        s1 += __shfl_xor_sync(0xffffffffu, s1, 1);
        s1 += __shfl_xor_sync(0xffffffffu, s1, 2);
        l0 += s0; l1 += s1;

        // ---- O += P @ V over this warp's 64 keys ----
        #pragma unroll
        for (int kk2 = 0; kk2 < 4; ++kk2) {
            const int j0 = kk2 * 2, j1 = j0 + 1;
            uint32_t ah[4], al[4];
            ah[0] = pack_bf16(s[j0][0], s[j0][1]);
            ah[1] = pack_bf16(s[j0][2], s[j0][3]);
            ah[2] = pack_bf16(s[j1][0], s[j1][1]);
            ah[3] = pack_bf16(s[j1][2], s[j1][3]);
            al[0] = pack_bf16(bf16_residual(s[j0][0]), bf16_residual(s[j0][1]));
            al[1] = pack_bf16(bf16_residual(s[j0][2]), bf16_residual(s[j0][3]));
            al[2] = pack_bf16(bf16_residual(s[j1][0]), bf16_residual(s[j1][1]));
            al[3] = pack_bf16(bf16_residual(s[j1][2]), bf16_residual(s[j1][3]));
            const int kwv = kh * 32 + kk2 * 8 + qq;
            #pragma unroll
            for (int jn = 0; jn < 8; ++jn) {
                const int hN = jn * 8 + g;
                uint32_t vh[2] = { VHw[hN * 68 + kwv], VHw[hN * 68 + kwv + 4] };
                uint32_t vl[2] = { VLw[hN * 68 + kwv], VLw[hN * 68 + kwv + 4] };
                mma_bf16(o[jn], ah, vh);
                mma_bf16(o[jn], ah, vl);
                mma_bf16(o[jn], al, vh);
            }
        }
    }

    // ---- merge key-halves through smem (overlay K region), write out ----
    __syncthreads();                          // everyone done with K/V buffer
    float* oB = reinterpret_cast<float*>(S + 4608);   // 64 x 68 over KH
    float* mB = reinterpret_cast<float*>(S + 9216);   // 64 over KL
    float* lB = mB + 64;

    if (kh == 1) {
        #pragma unroll
        for (int j = 0; j < 8; ++j) {
            const int h = j * 8 + q2;
            oB[(wbase + g) * 68 + h]         = o[j][0];
            oB[(wbase + g) * 68 + h + 1]     = o[j][1];
            oB[(wbase + 8 + g) * 68 + h]     = o[j][2];
            oB[(wbase + 8 + g) * 68 + h + 1] = o[j][3];
        }
        if (qq == 0) {
            mB[wbase + g] = m0;     lB[wbase + g] = l0;
            mB[wbase + 8 + g] = m1; lB[wbase + 8 + g] = l1;
        }
    }
    __syncthreads();

    if (kh == 0) {
        const int r0 = wbase + g, r1 = r0 + 8;
        const float mb0 = mB[r0], mb1 = mB[r1];
        const float mF0 = fmaxf(m0, mb0), mF1 = fmaxf(m1, mb1);
        const float aA0 = __expf(m0 - mF0), aB0 = __expf(mb0 - mF0);
        const float aA1 = __expf(m1 - mF1), aB1 = __expf(mb1 - mF1);
        const float i0 = 1.f / (l0 * aA0 + lB[r0] * aB0);
        const float i1 = 1.f / (l1 * aA1 + lB[r1] * aB1);
        const int gr0 = q0 + r0;
        const size_t ob = (size_t)b * TSEQ * HDIM;
        #pragma unroll
        for (int jn = 0; jn < 8; ++jn) {
            const int h = jn * 8 + q2;
            float2 v0, v1;
            v0.x = (o[jn][0] * aA0 + oB[r0 * 68 + h]     * aB0) * i0;
            v0.y = (o[jn][1] * aA0 + oB[r0 * 68 + h + 1] * aB0) * i0;
            v1.x = (o[jn][2] * aA1 + oB[r1 * 68 + h]     * aB1) * i1;
            v1.y = (o[jn][3] * aA1 + oB[r1 * 68 + h + 1] * aB1) * i1;
            *reinterpret_cast<float2*>(out + ob + (size_t)gr0 * 64 + h)       = v0;
            *reinterpret_cast<float2*>(out + ob + (size_t)(gr0 + 8) * 64 + h) = v1;
        }
    }
}

// ---------------------------------------------------------------------------
extern "C" void kernel_launch(void* const* d_in, const int* in_sizes, int n_in,
                              void* d_out, int out_size)
{
    const float* x  = (const float*)d_in[0];
    const float* Wg = (const float*)d_in[1];
    const float* bg = (const float*)d_in[2];
    const float* Wk = (const float*)d_in[3];
    const float* Wq = (const float*)d_in[4];
    const float* Wv = (const float*)d_in[5];
    float* out = (float*)d_out;

    cudaFuncSetAttribute(head_k1_gate_qkv,
                         cudaFuncAttributeMaxDynamicSharedMemorySize, K1_SMEM);
    cudaFuncSetAttribute(head_k2_attn,
                         cudaFuncAttributeMaxDynamicSharedMemorySize, K2_SMEM);

    head_k0_split<<<160, 256>>>(Wg, Wk, Wq, Wv);
    head_k1_gate_qkv<<<BT / 64, 256, K1_SMEM>>>(x, bg);
    head_k2_attn<<<dim3(8, 128), 256, K2_SMEM>>>(out);
}